// round 9
// baseline (speedup 1.0000x reference)
#include <cuda_runtime.h>
#include <cuda_bf16.h>
#include <cstdint>

// ---------------------------------------------------------------------------
// DMTet geometry, fully on-device. Outputs concatenated into d_out (float32):
//   [ verts (E*3) | faces (Fc*3) | verts_tetmesh (U*3) | tets_tetmesh (T*4) ]
// ---------------------------------------------------------------------------

#define MAXN 400000
#define MAXF 2000000
#define MAXS (6 * MAXF)            // max edge slots (6 per tet, slot = f*6+k)
#define MAXTE (12 * MAXF)          // max all_tets entries
#define PRESCAP (MAXN + MAXS)      // presence domain [0, N+E)
#define NBLK_MAX ((PRESCAP + 2047) / 2048 + 2)
#define NWORDS ((MAXN + 31) / 32)
#define NB256 ((MAXF + 255) / 256)
#define NBKT (2 * MAXN)            // buckets: (lo, hi-half) -> max lambda ~18
#define BROW 64                    // bucket row capacity; P(overflow) ~ 5e-17
#define NTILES_MAX ((NBKT + 7) / 8)

// classification bitmasks over tetindex
#define M_NTRI1 0x6996             // ti with 1 triangle
#define M_NTRI2 0x1668             // ti with 2 triangles
#define M_NTET1 0x0116             // valid ti with 1 tet

#define ST_VAL 0x3FFFFFFFFFFFFFFFULL

__device__ const int c_BE[12] = {0,1,0,2,0,3,1,2,1,3,2,3};
__device__ const int c_TRI[16][6] = {
    {-1,-1,-1,-1,-1,-1},{1,0,2,-1,-1,-1},{4,0,3,-1,-1,-1},{1,4,2,1,3,4},
    {3,1,5,-1,-1,-1},{2,3,0,2,5,3},{1,4,0,1,5,4},{4,2,5,-1,-1,-1},
    {4,5,2,-1,-1,-1},{4,1,0,4,5,1},{3,2,0,3,5,2},{1,3,5,-1,-1,-1},
    {4,1,2,4,3,1},{3,0,4,-1,-1,-1},{2,0,1,-1,-1,-1},{-1,-1,-1,-1,-1,-1}};
__device__ const int c_TET[16][12] = {
    {-1,-1,-1,-1,-1,-1,-1,-1,-1,-1,-1,-1},{0,4,5,6,-1,-1,-1,-1,-1,-1,-1,-1},
    {1,4,8,7,-1,-1,-1,-1,-1,-1,-1,-1},{7,1,8,6,5,1,7,6,5,0,1,6},
    {2,5,7,9,-1,-1,-1,-1,-1,-1,-1,-1},{4,0,6,7,9,0,7,6,7,0,9,2},
    {4,1,9,8,5,1,9,4,5,1,2,9},{6,0,1,2,8,6,1,2,9,6,8,2},
    {3,6,9,8,-1,-1,-1,-1,-1,-1,-1,-1},{5,0,4,8,5,0,8,3,5,8,9,3},
    {1,4,7,3,4,7,6,3,9,6,7,3},{0,1,5,3,5,1,9,3,5,1,7,9},
    {5,2,3,7,3,6,5,8,3,5,7,8},{0,4,7,8,0,3,8,7,0,3,7,2},
    {4,1,2,3,4,3,2,5,4,3,5,6},{0,1,2,3,-1,-1,-1,-1,-1,-1,-1,-1}};

// ---- scratch (static device memory; no runtime allocation) ----
__device__ unsigned int g_occbits[NWORDS];
__device__ unsigned char g_ti[MAXF];
__device__ int g_bcnt[NBKT];
__device__ __align__(16) unsigned long long g_bdata[(long long)NBKT * BROW];
__device__ int g_idxmap[MAXS];
__device__ unsigned long long g_tileStatus[NTILES_MAX];
__device__ __align__(16) int g_allTets[MAXTE];
__device__ __align__(16) unsigned char g_present[PRESCAP];
__device__ int g_presX[PRESCAP];
__device__ int g_bsums[NBLK_MAX];
__device__ ulonglong2 g_bsumsP[NB256 + 2];  // per-256-block cls sums / prefixes
// meta: 0 NT1  1 NT2  2 NTT1  3 INNER  4 E  5 U
//       6 facesOff(3E)  7 trows  8 vtOff  9 tetsOff
__device__ int g_meta[16];

__device__ __forceinline__ int occ_of(int v) {
    return (g_occbits[v >> 5] >> (v & 31)) & 1;
}

__device__ __forceinline__ unsigned long long pack16(int t) {
    return (unsigned long long)((M_NTRI1 >> t) & 1)
         | ((unsigned long long)((M_NTRI2 >> t) & 1) << 16)
         | ((unsigned long long)((M_NTET1 >> t) & 1) << 32)
         | ((unsigned long long)(t == 15 ? 1 : 0) << 48);
}

// Block-wide (256-thread) exclusive prefix over packed cls counters, plus the
// global per-block base from g_bsumsP. Every thread of the block must call.
__device__ __forceinline__ int4 cls_block_prefix(int t) {
    __shared__ unsigned long long sw[8];
    int lane = threadIdx.x & 31, wid = threadIdx.x >> 5;
    unsigned long long v = pack16(t);
    unsigned long long inc = v;
#pragma unroll
    for (int o = 1; o < 32; o <<= 1) {
        unsigned long long u = __shfl_up_sync(0xffffffffu, inc, o);
        if (lane >= o) inc += u;
    }
    if (lane == 31) sw[wid] = inc;
    __syncthreads();
    if (threadIdx.x == 0) {
        unsigned long long run = 0;
        for (int i = 0; i < 8; i++) { unsigned long long tmp = sw[i]; sw[i] = run; run += tmp; }
    }
    __syncthreads();
    unsigned long long ex = sw[wid] + inc - v;
    ulonglong2 bb = g_bsumsP[blockIdx.x];
    int4 r;
    r.x = (int)(ex & 0xffff) + (int)(bb.x & 0xffffffffULL);
    r.y = (int)((ex >> 16) & 0xffff) + (int)(bb.x >> 32);
    r.z = (int)((ex >> 32) & 0xffff) + (int)(bb.y & 0xffffffffULL);
    r.w = (int)((ex >> 48) & 0xffff) + (int)(bb.y >> 32);
    return r;
}

// ---------------------------------------------------------------------------
// scans (presence only)
// ---------------------------------------------------------------------------
// metaMode 2: presence total (U + tetsOff)
__global__ void k_scan_single(int* bsums, int nb, int metaMode) {
    __shared__ int sh[1024];
    int tid = threadIdx.x;
    int carry = 0;
    for (int base = 0; base < nb; base += 1024) {
        int i = base + tid;
        int v = (i < nb) ? bsums[i] : 0;
        sh[tid] = v; __syncthreads();
        for (int o = 1; o < 1024; o <<= 1) {
            int t = (tid >= o) ? sh[tid - o] : 0;
            __syncthreads(); sh[tid] += t; __syncthreads();
        }
        if (i < nb) bsums[i] = carry + sh[tid] - v;
        int tot = sh[1023]; __syncthreads();
        carry += tot;
    }
    if (tid == 0 && metaMode == 2) {
        g_meta[5] = carry;
        g_meta[9] = g_meta[8] + 3 * carry;
    }
}

// dynamic-n u8 scans over g_present, n = N + E (E from g_meta[4])
__global__ void k_scan_partial_u8d(int N, int* bsums) {
    __shared__ int sh[256];
    int n = N + g_meta[4];
    int b = blockIdx.x, tid = threadIdx.x;
    long long base = (long long)b * 2048 + tid * 8;
    int s = 0;
    if (base + 8 <= n) {
        unsigned long long v = *(const unsigned long long*)(g_present + base);
        s = __popcll(v);                    // bytes are 0/1
    } else {
        for (int j = 0; j < 8; j++) { long long i = base + j; if (i < n) s += g_present[i]; }
    }
    sh[tid] = s; __syncthreads();
    for (int o = 128; o > 0; o >>= 1) { if (tid < o) sh[tid] += sh[tid + o]; __syncthreads(); }
    if (tid == 0) bsums[b] = sh[0];
}

__global__ void k_scan_final_u8d(int N, const int* bsums) {
    __shared__ int sh[256];
    int n = N + g_meta[4];
    int b = blockIdx.x, tid = threadIdx.x;
    long long base = (long long)b * 2048 + tid * 8;
    int v[8]; int s = 0;
    if (base + 8 <= n) {
        unsigned long long vv = *(const unsigned long long*)(g_present + base);
#pragma unroll
        for (int j = 0; j < 8; j++) { v[j] = (int)((vv >> (8 * j)) & 0xff); s += v[j]; }
    } else {
#pragma unroll
        for (int j = 0; j < 8; j++) { long long i = base + j; v[j] = (i < n) ? (int)g_present[i] : 0; s += v[j]; }
    }
    sh[tid] = s; __syncthreads();
    for (int o = 1; o < 256; o <<= 1) {
        int t = (tid >= o) ? sh[tid - o] : 0;
        __syncthreads(); sh[tid] += t; __syncthreads();
    }
    int run = bsums[b] + sh[tid] - s;
#pragma unroll
    for (int j = 0; j < 8; j++) { long long i = base + j; if (i < n) g_presX[i] = run; run += v[j]; }
}

// single-block scan over packed per-block cls sums (2 u64 components)
__global__ void k_scan_singleP(int nb) {
    __shared__ unsigned long long sh[1024];
    unsigned long long* bs = (unsigned long long*)g_bsumsP;
    int tid = threadIdx.x;
    for (int c = 0; c < 2; c++) {
        unsigned long long carry = 0;
        for (int base = 0; base < nb; base += 1024) {
            int i = base + tid;
            unsigned long long v = (i < nb) ? bs[i * 2 + c] : 0;
            sh[tid] = v; __syncthreads();
            for (int o = 1; o < 1024; o <<= 1) {
                unsigned long long t = (tid >= o) ? sh[tid - o] : 0;
                __syncthreads(); sh[tid] += t; __syncthreads();
            }
            if (i < nb) bs[i * 2 + c] = carry + sh[tid] - v;
            unsigned long long tot = sh[1023]; __syncthreads();
            carry += tot;
        }
        if (tid == 0) {
            if (c == 0) { g_meta[0] = (int)(carry & 0xffffffffULL); g_meta[1] = (int)(carry >> 32); }
            else        { g_meta[2] = (int)(carry & 0xffffffffULL); g_meta[3] = (int)(carry >> 32); }
        }
        __syncthreads();
    }
}

// ---------------------------------------------------------------------------
// pipeline kernels
// ---------------------------------------------------------------------------
__global__ void k_occbits(const float* sdf, const float* th, int N, int NW, int NT) {
    int i = blockIdx.x * blockDim.x + threadIdx.x;
    float t = th[0];
    bool p = false;
    if (i < N) { float s = sdf[i]; p = (s > 0.f && s <= t); }
    unsigned m = __ballot_sync(0xffffffffu, p);
    if ((threadIdx.x & 31) == 0 && (i >> 5) < NW) g_occbits[i >> 5] = m;
    if (i < N) {                    // fused bucket-count reset (2 buckets per vertex)
        g_bcnt[2 * i] = 0;
        g_bcnt[2 * i + 1] = 0;
    }
    if (i < NT) g_tileStatus[i] = 0;  // fused look-back status reset
}

// One tet pass: tetindex + per-block packed cls sums + direct edge scatter
// into the fixed-stride bucket matrix. Bucket = lo*2 + (hi >= NHALF) to cap
// the skewed per-lo load (lambda <= ~18 per bucket). Slot id = f*6+k.
__global__ void k_ti_scatter(const int4* tet, int F, int NHALF) {
    __shared__ unsigned long long sw[8];
    int f = blockIdx.x * 256 + threadIdx.x;
    int lane = threadIdx.x & 31, wid = threadIdx.x >> 5;
    int t = 0;
    if (f < F) {
        int4 q = tet[f];
        t = occ_of(q.x) | (occ_of(q.y) << 1) | (occ_of(q.z) << 2) | (occ_of(q.w) << 3);
        g_ti[f] = (unsigned char)t;
        if (t != 0 && t != 15) {
            int qq[4] = {q.x, q.y, q.z, q.w};
#pragma unroll
            for (int k = 0; k < 6; k++) {
                int a = qq[c_BE[2 * k]], b = qq[c_BE[2 * k + 1]];
                int lo = a < b ? a : b, hi = a < b ? b : a;
                int bkt = (lo << 1) | (hi >= NHALF ? 1 : 0);
                int idx = atomicAdd(&g_bcnt[bkt], 1);
                if (idx < BROW)
                    g_bdata[(long long)bkt * BROW + idx] =
                        ((unsigned long long)(unsigned)hi << 32) | (unsigned)(f * 6 + k);
            }
        }
    }
    unsigned long long v = pack16(t);
#pragma unroll
    for (int o = 16; o > 0; o >>= 1) v += __shfl_down_sync(0xffffffffu, v, o);
    if (lane == 0) sw[wid] = v;
    __syncthreads();
    if (threadIdx.x == 0) {
        unsigned long long tot = 0;
        for (int i = 0; i < 8; i++) tot += sw[i];
        ulonglong2 r;
        r.x = (tot & 0xffffULL) | (((tot >> 16) & 0xffffULL) << 32);
        r.y = ((tot >> 32) & 0xffffULL) | (((tot >> 48) & 0xffffULL) << 32);
        g_bsumsP[blockIdx.x] = r;
    }
}

// Single-pass fused bucket kernel: per-warp crossing detection (match_any),
// block scan of 8 warp counts, decoupled look-back for the global edge-id
// base, then idxmap assignment + interpolated vertex emission. Last tile
// writes E + derived meta offsets.
__global__ void k_bucket(const float* pos, const float* sdf, const float* th,
                         float* out, int NB) {
    __shared__ int wcnt[8], wexc[8];
    __shared__ int sAgg;
    __shared__ long long sBase;
    int tile = blockIdx.x;
    int warp = threadIdx.x >> 5, lane = threadIdx.x & 31;
    int b = tile * 8 + warp;
    bool active = (b < NB);

    // ---- count phase ----
    int n = 0, occa = 0, cnt = 0;
    long long s = 0;
    int hi = -1, slot = 0, leaderLane = 0, rank = 0;
    bool cross = false;
    if (active) {
        n = min(g_bcnt[b], BROW);
        s = (long long)b * BROW;
        occa = occ_of(b >> 1);
    }
    if (active && n > 0 && n <= 32) {
        if (lane < n) {
            unsigned long long d = g_bdata[s + lane];
            hi = (int)(d >> 32);
            slot = (int)(d & 0xffffffffu);
        }
        unsigned peers = __match_any_sync(0xffffffffu, hi);
        leaderLane = __ffs(peers) - 1;
        bool leader = (lane < n) && (lane == leaderLane);
        cross = leader && ((occa ^ occ_of(hi)) != 0);
        unsigned crossB = __ballot_sync(0xffffffffu, cross);
        cnt = __popc(crossB);
        // rank among crossing leaders, ordered by hi ascending
        unsigned m = crossB;
        while (m) {
            int j = __ffs(m) - 1; m &= m - 1;
            int hj = __shfl_sync(0xffffffffu, hi, j);
            if (cross && hj < hi) rank++;
        }
    } else if (active && n > 32) {
        if (lane == 0) {
            // rare fallback: in-place sort (row stays sorted for emit phase)
            for (int i = 1; i < n; i++) {
                unsigned long long key = g_bdata[s + i];
                int j = i - 1;
                while (j >= 0 && g_bdata[s + j] > key) { g_bdata[s + j + 1] = g_bdata[s + j]; j--; }
                g_bdata[s + j + 1] = key;
            }
            long long prev = -1; int c = 0;
            for (int i = 0; i < n; i++) {
                int hv = (int)(g_bdata[s + i] >> 32);
                if (hv != prev) { c += occa ^ occ_of(hv); prev = hv; }
            }
            cnt = c;
        }
        cnt = __shfl_sync(0xffffffffu, cnt, 0);
    }
    if (lane == 0) wcnt[warp] = cnt;
    __syncthreads();

    // ---- block scan of 8 warp counts + publish aggregate ----
    if (threadIdx.x == 0) {
        int run = 0;
        for (int i = 0; i < 8; i++) { wexc[i] = run; run += wcnt[i]; }
        sAgg = run;
        atomicExch(&g_tileStatus[tile], (1ULL << 62) | (unsigned long long)run);
    }
    __syncthreads();

    // ---- decoupled look-back (warp 0) ----
    if (warp == 0) {
        long long excl = 0;
        if (tile > 0) {
            int look = tile - 1;
            while (true) {
                int idx = look - lane;
                unsigned long long st;
                if (idx >= 0) {
                    st = *((volatile unsigned long long*)g_tileStatus + idx);
                    while ((st >> 62) == 0)
                        st = *((volatile unsigned long long*)g_tileStatus + idx);
                } else {
                    st = (2ULL << 62);
                }
                unsigned flag = (unsigned)(st >> 62);
                long long val = (long long)(st & ST_VAL);
                unsigned incB = __ballot_sync(0xffffffffu, flag == 2);
                int firstInc = incB ? (__ffs(incB) - 1) : 32;
                long long contrib = (lane <= firstInc) ? val : 0;
#pragma unroll
                for (int o = 16; o > 0; o >>= 1)
                    contrib += __shfl_down_sync(0xffffffffu, contrib, o);
                contrib = __shfl_sync(0xffffffffu, contrib, 0);
                excl += contrib;
                if (incB) break;
                look -= 32;
            }
        }
        if (lane == 0) {
            long long inc = excl + sAgg;
            atomicExch(&g_tileStatus[tile], (2ULL << 62) | (unsigned long long)inc);
            sBase = excl;
            if (tile == (int)gridDim.x - 1) {
                int E = (int)inc;
                int NT1 = g_meta[0], NT2 = g_meta[1], NTT1 = g_meta[2], INNER = g_meta[3];
                int NTT3 = NT1 + NT2 - NTT1;
                g_meta[4] = E;
                g_meta[6] = 3 * E;
                g_meta[7] = NTT1 + 3 * NTT3 + INNER;
                g_meta[8] = 3 * E + 3 * (NT1 + 2 * NT2);
            }
        }
    }
    __syncthreads();

    // ---- emit phase ----
    int base = (int)(sBase + wexc[warp]);
    int lo = b >> 1;
    if (active && n > 0 && n <= 32) {
        int eid = cross ? (base + rank) : -1;
        int mv = __shfl_sync(0xffffffffu, eid, leaderLane);
        if (lane < n) g_idxmap[slot] = mv;
        if (cross) {
            float t = th[0];
            float s0 = sdf[lo], s1 = sdf[hi];
            if (s0 > 0.f && s1 > 0.f) { s0 -= t; s1 -= t; }
            float inv = 1.f / (s0 - s1);
            float w0 = -s1 * inv, w1 = s0 * inv;
#pragma unroll
            for (int c = 0; c < 3; c++)
                out[eid * 3 + c] = pos[lo * 3 + c] * w0 + pos[hi * 3 + c] * w1;
        }
    } else if (active && n > 32) {
        if (lane == 0) {
            long long prev = -1; int c = 0, mv = -1;
            for (int i = 0; i < n; i++) {
                unsigned long long d = g_bdata[s + i];
                int hv = (int)(d >> 32);
                int sl = (int)(d & 0xffffffffu);
                if (hv != prev) {
                    if (occa ^ occ_of(hv)) {
                        int eid = base + c;
                        float t = th[0];
                        float s0 = sdf[lo], s1 = sdf[hv];
                        if (s0 > 0.f && s1 > 0.f) { s0 -= t; s1 -= t; }
                        float inv = 1.f / (s0 - s1);
                        float w0 = -s1 * inv, w1 = s0 * inv;
                        for (int cc = 0; cc < 3; cc++)
                            out[eid * 3 + cc] = pos[lo * 3 + cc] * w0 + pos[hv * 3 + cc] * w1;
                        mv = eid; c++;
                    } else mv = -1;
                    prev = hv;
                }
                g_idxmap[sl] = mv;
            }
        }
    }
}

__global__ void k_fill_present(int N) {
    int n2 = N + g_meta[4];
    int nw = (n2 + 3) >> 2;
    int i = blockIdx.x * blockDim.x + threadIdx.x;
    if (i < nw) ((int*)g_present)[i] = 0;
}

// fused: faces emission + tetmesh connectivity build + presence marking
__global__ void k_emit(const int4* tet, float* out, int F, int N) {
    int f = blockIdx.x * 256 + threadIdx.x;
    int t = (f < F) ? (int)g_ti[f] : 0;
    int4 cls = cls_block_prefix(t);
    if (f >= F || t == 0) return;
    int4 q = tet[f];
    int qq[4] = {q.x, q.y, q.z, q.w};
    int4* tets4 = (int4*)g_allTets;
    if (t == 15) {
        int NTT3 = g_meta[0] + g_meta[1] - g_meta[2];
        int row = g_meta[2] + 3 * NTT3 + cls.w;
        tets4[row] = q;
#pragma unroll
        for (int j = 0; j < 4; j++) g_present[qq[j]] = 1;
        return;
    }
    int base6 = f * 6;
    int foff = g_meta[6];
    if ((M_NTRI1 >> t) & 1) {
        int row = cls.x;
#pragma unroll
        for (int j = 0; j < 3; j++)
            out[foff + row * 3 + j] = (float)g_idxmap[base6 + c_TRI[t][j]];
    } else {
        int row = g_meta[0] + 2 * cls.y;
#pragma unroll
        for (int j = 0; j < 6; j++)
            out[foff + row * 3 + j] = (float)g_idxmap[base6 + c_TRI[t][j]];
    }
    if ((M_NTET1 >> t) & 1) {
        int row = cls.z;
        int v[4];
#pragma unroll
        for (int j = 0; j < 4; j++) {
            int e = c_TET[t][j];
            v[j] = (e < 4) ? qq[e] : (g_idxmap[base6 + e - 4] + N);
            g_present[v[j]] = 1;
        }
        tets4[row] = make_int4(v[0], v[1], v[2], v[3]);
    } else {
        int row = g_meta[2] + 3 * ((cls.x + cls.y) - cls.z);
#pragma unroll
        for (int rr = 0; rr < 3; rr++) {
            int v[4];
#pragma unroll
            for (int j = 0; j < 4; j++) {
                int e = c_TET[t][rr * 4 + j];
                v[j] = (e < 4) ? qq[e] : (g_idxmap[base6 + e - 4] + N);
                g_present[v[j]] = 1;
            }
            tets4[row + rr] = make_int4(v[0], v[1], v[2], v[3]);
        }
    }
}

__global__ void k_vt(const float* pos, float* out, int N) {
    int n2 = N + g_meta[4];
    int idx = blockIdx.x * blockDim.x + threadIdx.x;
    if (idx >= n2) return;
    if (!g_present[idx]) return;
    int uid = g_presX[idx];
    float x, y, z;
    if (idx < N) {
        x = pos[idx * 3 + 0]; y = pos[idx * 3 + 1]; z = pos[idx * 3 + 2];
    } else {
        int e = idx - N;
        x = out[e * 3 + 0]; y = out[e * 3 + 1]; z = out[e * 3 + 2];
    }
    int o = g_meta[8];
    out[o + uid * 3 + 0] = x;
    out[o + uid * 3 + 1] = y;
    out[o + uid * 3 + 2] = z;
}

__global__ void k_tout(float* out) {
    int row = blockIdx.x * blockDim.x + threadIdx.x;
    if (row >= g_meta[7]) return;
    int4 v = ((const int4*)g_allTets)[row];
    int o = g_meta[9] + row * 4;
    out[o + 0] = (float)g_presX[v.x];
    out[o + 1] = (float)g_presX[v.y];
    out[o + 2] = (float)g_presX[v.z];
    out[o + 3] = (float)g_presX[v.w];
}

// ---------------------------------------------------------------------------
// host launcher
// ---------------------------------------------------------------------------
static inline int gb(long long n) { return (int)((n + 255) / 256); }

extern "C" void kernel_launch(void* const* d_in, const int* in_sizes, int n_in,
                              void* d_out, int out_size) {
    const float* pos = (const float*)d_in[0];
    const float* sdf = (const float*)d_in[1];
    const int4* tet = (const int4*)d_in[2];
    const float* thick = (const float*)d_in[3];
    float* out = (float*)d_out;

    int N = in_sizes[1];
    int F = in_sizes[2] / 4;
    if (N > MAXN) N = MAXN;
    if (F > MAXF) F = MAXF;
    int NW = (N + 31) / 32;
    int PL = N + MAXS;
    int NB = 2 * N;                    // buckets (lo, hi-half)
    int NHALF = N / 2;
    int NT = (NB + 7) / 8;             // look-back tiles

    int* p_bsums;
    cudaGetSymbolAddress((void**)&p_bsums, g_bsums);

    int nbF = (F + 255) / 256;          // tet-domain blocks
    int nbP = (PL + 2047) / 2048;       // presence scan blocks (worst case)

    // 1. occupancy bitmask (+bcnt & tile-status reset), fused ti+cls+scatter
    k_occbits<<<gb((long long)NW * 32), 256>>>(sdf, thick, N, NW, NT);
    k_ti_scatter<<<nbF, 256>>>(tet, F, NHALF);
    k_scan_singleP<<<1, 1024>>>(nbF);   // -> per-block cls bases + meta[0..3]

    // 2. single-pass bucket kernel: count + look-back scan + idxmap + verts
    k_bucket<<<NT, 256>>>(pos, sdf, thick, out, NB);

    // 3. presence reset over [0, N+E), then faces + tets + marks (fused)
    k_fill_present<<<gb(PL / 4), 256>>>(N);
    k_emit<<<nbF, 256>>>(tet, out, F, N);

    // 4. presence scan over [0, N+E) -> sorted-unique ids (+U, tetsOff)
    k_scan_partial_u8d<<<nbP, 256>>>(N, p_bsums);
    k_scan_single<<<1, 1024>>>(p_bsums, nbP, 2);
    k_scan_final_u8d<<<nbP, 256>>>(N, p_bsums);

    // 5. verts_tetmesh (region 2) + tets_tetmesh (region 3)
    k_vt<<<gb(PL), 256>>>(pos, out, N);
    k_tout<<<gb(MAXTE / 4), 256>>>(out);
}

// round 11
// speedup vs baseline: 3.9428x; 3.9428x over previous
#include <cuda_runtime.h>
#include <cuda_bf16.h>
#include <cstdint>

// ---------------------------------------------------------------------------
// DMTet geometry, fully on-device. Outputs concatenated into d_out (float32):
//   [ verts (E*3) | faces (Fc*3) | verts_tetmesh (U*3) | tets_tetmesh (T*4) ]
// ---------------------------------------------------------------------------

#define MAXN 400000
#define MAXF 2000000
#define MAXS (6 * MAXF)            // max edge slots (6 per tet, slot = f*6+k)
#define MAXTE (12 * MAXF)          // max all_tets entries
#define PRESCAP (MAXN + MAXS)      // presence domain [0, N+E)
#define NBLK_MAX ((PRESCAP + 2047) / 2048 + 2)
#define NWORDS ((MAXN + 31) / 32)
#define NB256 ((MAXF + 255) / 256)
#define NBKT (2 * MAXN)            // buckets: (lo, hi-half) -> max lambda ~18
#define BROW 64                    // bucket row capacity; P(overflow) ~ 5e-17

// classification bitmasks over tetindex
#define M_NTRI1 0x6996             // ti with 1 triangle
#define M_NTRI2 0x1668             // ti with 2 triangles
#define M_NTET1 0x0116             // valid ti with 1 tet

__device__ const int c_BE[12] = {0,1,0,2,0,3,1,2,1,3,2,3};
__device__ const int c_TRI[16][6] = {
    {-1,-1,-1,-1,-1,-1},{1,0,2,-1,-1,-1},{4,0,3,-1,-1,-1},{1,4,2,1,3,4},
    {3,1,5,-1,-1,-1},{2,3,0,2,5,3},{1,4,0,1,5,4},{4,2,5,-1,-1,-1},
    {4,5,2,-1,-1,-1},{4,1,0,4,5,1},{3,2,0,3,5,2},{1,3,5,-1,-1,-1},
    {4,1,2,4,3,1},{3,0,4,-1,-1,-1},{2,0,1,-1,-1,-1},{-1,-1,-1,-1,-1,-1}};
__device__ const int c_TET[16][12] = {
    {-1,-1,-1,-1,-1,-1,-1,-1,-1,-1,-1,-1},{0,4,5,6,-1,-1,-1,-1,-1,-1,-1,-1},
    {1,4,8,7,-1,-1,-1,-1,-1,-1,-1,-1},{7,1,8,6,5,1,7,6,5,0,1,6},
    {2,5,7,9,-1,-1,-1,-1,-1,-1,-1,-1},{4,0,6,7,9,0,7,6,7,0,9,2},
    {4,1,9,8,5,1,9,4,5,1,2,9},{6,0,1,2,8,6,1,2,9,6,8,2},
    {3,6,9,8,-1,-1,-1,-1,-1,-1,-1,-1},{5,0,4,8,5,0,8,3,5,8,9,3},
    {1,4,7,3,4,7,6,3,9,6,7,3},{0,1,5,3,5,1,9,3,5,1,7,9},
    {5,2,3,7,3,6,5,8,3,5,7,8},{0,4,7,8,0,3,8,7,0,3,7,2},
    {4,1,2,3,4,3,2,5,4,3,5,6},{0,1,2,3,-1,-1,-1,-1,-1,-1,-1,-1}};

// ---- scratch (static device memory; no runtime allocation) ----
__device__ unsigned int g_occbits[NWORDS];
__device__ unsigned char g_ti[MAXF];
__device__ int g_bcnt[NBKT];
__device__ __align__(16) unsigned long long g_bdata[(long long)NBKT * BROW];
__device__ int g_idxmap[MAXS];
__device__ int g_crossCnt[NBKT];
__device__ int g_crossX[NBKT];
__device__ __align__(16) int g_allTets[MAXTE];
__device__ __align__(16) unsigned char g_present[PRESCAP];
__device__ int g_presX[PRESCAP];
__device__ int g_bsums[NBLK_MAX];
__device__ ulonglong2 g_bsumsP[NB256 + 2];  // per-256-block cls sums / prefixes
// meta: 0 NT1  1 NT2  2 NTT1  3 INNER  4 E  5 U
//       6 facesOff(3E)  7 trows  8 vtOff  9 tetsOff
__device__ int g_meta[16];

__device__ __forceinline__ int occ_of(int v) {
    return (g_occbits[v >> 5] >> (v & 31)) & 1;
}

__device__ __forceinline__ unsigned long long pack16(int t) {
    return (unsigned long long)((M_NTRI1 >> t) & 1)
         | ((unsigned long long)((M_NTRI2 >> t) & 1) << 16)
         | ((unsigned long long)((M_NTET1 >> t) & 1) << 32)
         | ((unsigned long long)(t == 15 ? 1 : 0) << 48);
}

// Block-wide (256-thread) exclusive prefix over packed cls counters, plus the
// global per-block base from g_bsumsP. Every thread of the block must call.
__device__ __forceinline__ int4 cls_block_prefix(int t) {
    __shared__ unsigned long long sw[8];
    int lane = threadIdx.x & 31, wid = threadIdx.x >> 5;
    unsigned long long v = pack16(t);
    unsigned long long inc = v;
#pragma unroll
    for (int o = 1; o < 32; o <<= 1) {
        unsigned long long u = __shfl_up_sync(0xffffffffu, inc, o);
        if (lane >= o) inc += u;
    }
    if (lane == 31) sw[wid] = inc;
    __syncthreads();
    if (threadIdx.x == 0) {
        unsigned long long run = 0;
        for (int i = 0; i < 8; i++) { unsigned long long tmp = sw[i]; sw[i] = run; run += tmp; }
    }
    __syncthreads();
    unsigned long long ex = sw[wid] + inc - v;
    ulonglong2 bb = g_bsumsP[blockIdx.x];
    int4 r;
    r.x = (int)(ex & 0xffff) + (int)(bb.x & 0xffffffffULL);
    r.y = (int)((ex >> 16) & 0xffff) + (int)(bb.x >> 32);
    r.z = (int)((ex >> 32) & 0xffff) + (int)(bb.y & 0xffffffffULL);
    r.w = (int)((ex >> 48) & 0xffff) + (int)(bb.y >> 32);
    return r;
}

// ---------------------------------------------------------------------------
// scans
// ---------------------------------------------------------------------------
__global__ void k_scan_partial_int(const int* in, int n, int* bsums) {
    __shared__ int sh[256];
    int b = blockIdx.x, tid = threadIdx.x;
    int base = b * 2048 + tid * 8;
    int s = 0;
#pragma unroll
    for (int j = 0; j < 8; j++) { int i = base + j; if (i < n) s += in[i]; }
    sh[tid] = s; __syncthreads();
    for (int o = 128; o > 0; o >>= 1) { if (tid < o) sh[tid] += sh[tid + o]; __syncthreads(); }
    if (tid == 0) bsums[b] = sh[0];
}

// metaMode: 1 crossCnt total (E + derived offsets), 2 presence total (U + tetsOff)
__global__ void k_scan_single(int* bsums, int nb, int metaMode) {
    __shared__ int sh[1024];
    int tid = threadIdx.x;
    int carry = 0;
    for (int base = 0; base < nb; base += 1024) {
        int i = base + tid;
        int v = (i < nb) ? bsums[i] : 0;
        sh[tid] = v; __syncthreads();
        for (int o = 1; o < 1024; o <<= 1) {
            int t = (tid >= o) ? sh[tid - o] : 0;
            __syncthreads(); sh[tid] += t; __syncthreads();
        }
        if (i < nb) bsums[i] = carry + sh[tid] - v;
        int tot = sh[1023]; __syncthreads();
        carry += tot;
    }
    if (tid == 0) {
        if (metaMode == 1) {
            int E = carry;
            int NT1 = g_meta[0], NT2 = g_meta[1], NTT1 = g_meta[2], INNER = g_meta[3];
            int NTT3 = NT1 + NT2 - NTT1;
            g_meta[4] = E;
            g_meta[6] = 3 * E;
            g_meta[7] = NTT1 + 3 * NTT3 + INNER;
            g_meta[8] = 3 * E + 3 * (NT1 + 2 * NT2);
        } else if (metaMode == 2) {
            g_meta[5] = carry;
            g_meta[9] = g_meta[8] + 3 * carry;
        }
    }
}

__global__ void k_scan_final_int(const int* in, int n, const int* bsums, int* outp) {
    __shared__ int sh[256];
    int b = blockIdx.x, tid = threadIdx.x;
    int base = b * 2048 + tid * 8;
    int v[8]; int s = 0;
#pragma unroll
    for (int j = 0; j < 8; j++) { int i = base + j; v[j] = (i < n) ? in[i] : 0; s += v[j]; }
    sh[tid] = s; __syncthreads();
    for (int o = 1; o < 256; o <<= 1) {
        int t = (tid >= o) ? sh[tid - o] : 0;
        __syncthreads(); sh[tid] += t; __syncthreads();
    }
    int run = bsums[b] + sh[tid] - s;
#pragma unroll
    for (int j = 0; j < 8; j++) { int i = base + j; if (i < n) outp[i] = run; run += v[j]; }
}

// dynamic-n u8 scans over g_present, n = N + E (E from g_meta[4])
__global__ void k_scan_partial_u8d(int N, int* bsums) {
    __shared__ int sh[256];
    int n = N + g_meta[4];
    int b = blockIdx.x, tid = threadIdx.x;
    long long base = (long long)b * 2048 + tid * 8;
    int s = 0;
    if (base + 8 <= n) {
        unsigned long long v = *(const unsigned long long*)(g_present + base);
        s = __popcll(v);                    // bytes are 0/1
    } else {
        for (int j = 0; j < 8; j++) { long long i = base + j; if (i < n) s += g_present[i]; }
    }
    sh[tid] = s; __syncthreads();
    for (int o = 128; o > 0; o >>= 1) { if (tid < o) sh[tid] += sh[tid + o]; __syncthreads(); }
    if (tid == 0) bsums[b] = sh[0];
}

__global__ void k_scan_final_u8d(int N, const int* bsums) {
    __shared__ int sh[256];
    int n = N + g_meta[4];
    int b = blockIdx.x, tid = threadIdx.x;
    long long base = (long long)b * 2048 + tid * 8;
    int v[8]; int s = 0;
    if (base + 8 <= n) {
        unsigned long long vv = *(const unsigned long long*)(g_present + base);
#pragma unroll
        for (int j = 0; j < 8; j++) { v[j] = (int)((vv >> (8 * j)) & 0xff); s += v[j]; }
    } else {
#pragma unroll
        for (int j = 0; j < 8; j++) { long long i = base + j; v[j] = (i < n) ? (int)g_present[i] : 0; s += v[j]; }
    }
    sh[tid] = s; __syncthreads();
    for (int o = 1; o < 256; o <<= 1) {
        int t = (tid >= o) ? sh[tid - o] : 0;
        __syncthreads(); sh[tid] += t; __syncthreads();
    }
    int run = bsums[b] + sh[tid] - s;
#pragma unroll
    for (int j = 0; j < 8; j++) { long long i = base + j; if (i < n) g_presX[i] = run; run += v[j]; }
}

// single-block scan over packed per-block cls sums (2 u64 components)
__global__ void k_scan_singleP(int nb) {
    __shared__ unsigned long long sh[1024];
    unsigned long long* bs = (unsigned long long*)g_bsumsP;
    int tid = threadIdx.x;
    for (int c = 0; c < 2; c++) {
        unsigned long long carry = 0;
        for (int base = 0; base < nb; base += 1024) {
            int i = base + tid;
            unsigned long long v = (i < nb) ? bs[i * 2 + c] : 0;
            sh[tid] = v; __syncthreads();
            for (int o = 1; o < 1024; o <<= 1) {
                unsigned long long t = (tid >= o) ? sh[tid - o] : 0;
                __syncthreads(); sh[tid] += t; __syncthreads();
            }
            if (i < nb) bs[i * 2 + c] = carry + sh[tid] - v;
            unsigned long long tot = sh[1023]; __syncthreads();
            carry += tot;
        }
        if (tid == 0) {
            if (c == 0) { g_meta[0] = (int)(carry & 0xffffffffULL); g_meta[1] = (int)(carry >> 32); }
            else        { g_meta[2] = (int)(carry & 0xffffffffULL); g_meta[3] = (int)(carry >> 32); }
        }
        __syncthreads();
    }
}

// ---------------------------------------------------------------------------
// pipeline kernels
// ---------------------------------------------------------------------------
__global__ void k_occbits(const float* sdf, const float* th, int N, int NW) {
    int i = blockIdx.x * blockDim.x + threadIdx.x;
    float t = th[0];
    bool p = false;
    if (i < N) { float s = sdf[i]; p = (s > 0.f && s <= t); }
    unsigned m = __ballot_sync(0xffffffffu, p);
    if ((threadIdx.x & 31) == 0 && (i >> 5) < NW) g_occbits[i >> 5] = m;
    if (i < N) {                    // fused bucket-count reset (2 buckets per vertex)
        g_bcnt[2 * i] = 0;
        g_bcnt[2 * i + 1] = 0;
    }
}

// One tet pass: tetindex + per-block packed cls sums + direct edge scatter
// into the fixed-stride bucket matrix. Bucket = lo*2 + (hi >= NHALF) to cap
// the skewed per-lo load (lambda <= ~18 per bucket). Slot id = f*6+k.
__global__ void k_ti_scatter(const int4* tet, int F, int NHALF) {
    __shared__ unsigned long long sw[8];
    int f = blockIdx.x * 256 + threadIdx.x;
    int lane = threadIdx.x & 31, wid = threadIdx.x >> 5;
    int t = 0;
    if (f < F) {
        int4 q = tet[f];
        t = occ_of(q.x) | (occ_of(q.y) << 1) | (occ_of(q.z) << 2) | (occ_of(q.w) << 3);
        g_ti[f] = (unsigned char)t;
        if (t != 0 && t != 15) {
            int qq[4] = {q.x, q.y, q.z, q.w};
#pragma unroll
            for (int k = 0; k < 6; k++) {
                int a = qq[c_BE[2 * k]], b = qq[c_BE[2 * k + 1]];
                int lo = a < b ? a : b, hi = a < b ? b : a;
                int bkt = (lo << 1) | (hi >= NHALF ? 1 : 0);
                int idx = atomicAdd(&g_bcnt[bkt], 1);
                if (idx < BROW)
                    g_bdata[(long long)bkt * BROW + idx] =
                        ((unsigned long long)(unsigned)hi << 32) | (unsigned)(f * 6 + k);
            }
        }
    }
    unsigned long long v = pack16(t);
#pragma unroll
    for (int o = 16; o > 0; o >>= 1) v += __shfl_down_sync(0xffffffffu, v, o);
    if (lane == 0) sw[wid] = v;
    __syncthreads();
    if (threadIdx.x == 0) {
        unsigned long long tot = 0;
        for (int i = 0; i < 8; i++) tot += sw[i];
        ulonglong2 r;
        r.x = (tot & 0xffffULL) | (((tot >> 16) & 0xffffULL) << 32);
        r.y = ((tot >> 32) & 0xffffULL) | (((tot >> 48) & 0xffffULL) << 32);
        g_bsumsP[blockIdx.x] = r;
    }
}

// Phase 1: distinct crossing count per bucket — no sort, match_any + ballot.
__global__ void k_bcount(int NB) {
    int lane = threadIdx.x & 31;
    int b = (blockIdx.x * blockDim.x + threadIdx.x) >> 5;
    if (b >= NB) return;
    int n = min(g_bcnt[b], BROW);
    if (n == 0) { if (lane == 0) g_crossCnt[b] = 0; return; }
    long long s = (long long)b * BROW;
    int occa = occ_of(b >> 1);
    if (n <= 32) {
        int hi = -1;
        if (lane < n) hi = (int)(g_bdata[s + lane] >> 32);
        unsigned peers = __match_any_sync(0xffffffffu, hi);
        bool leader = (lane < n) && (lane == __ffs(peers) - 1);
        bool cross = leader && ((occa ^ occ_of(hi)) != 0);
        int c = __popc(__ballot_sync(0xffffffffu, cross));
        if (lane == 0) g_crossCnt[b] = c;
    } else if (lane == 0) {
        // rare fallback: in-place sort (leaves row sorted for k_bemit)
        for (int i = 1; i < n; i++) {
            unsigned long long key = g_bdata[s + i];
            int j = i - 1;
            while (j >= 0 && g_bdata[s + j] > key) { g_bdata[s + j + 1] = g_bdata[s + j]; j--; }
            g_bdata[s + j + 1] = key;
        }
        long long prev = -1; int c = 0;
        for (int i = 0; i < n; i++) {
            int hv = (int)(g_bdata[s + i] >> 32);
            if (hv != prev) { c += occa ^ occ_of(hv); prev = hv; }
        }
        g_crossCnt[b] = c;
    }
}

// Phase 2: sort-free. match_any groups duplicates; crossing leaders get rank
// by counting crossing leaders with smaller hi; dup lanes take leader's eid
// via shfl. Fused interpolated vertex emission.
__global__ void k_bemit(const float* pos, const float* sdf, const float* th,
                        float* out, int NB) {
    int lane = threadIdx.x & 31;
    int b = (blockIdx.x * blockDim.x + threadIdx.x) >> 5;
    if (b >= NB) return;
    int n = min(g_bcnt[b], BROW);
    if (n == 0) return;
    long long s = (long long)b * BROW;
    int base = g_crossX[b];
    int lo = b >> 1;
    int occa = occ_of(lo);
    if (n <= 32) {
        int hi = -1, slot = 0;
        if (lane < n) {
            unsigned long long d = g_bdata[s + lane];
            hi = (int)(d >> 32);
            slot = (int)(d & 0xffffffffu);
        }
        unsigned peers = __match_any_sync(0xffffffffu, hi);
        int leaderLane = __ffs(peers) - 1;
        bool leader = (lane < n) && (lane == leaderLane);
        bool cross = leader && ((occa ^ occ_of(hi)) != 0);
        unsigned crossB = __ballot_sync(0xffffffffu, cross);
        // rank among crossing leaders, ordered by hi ascending
        int rank = 0;
        unsigned m = crossB;
        while (m) {
            int j = __ffs(m) - 1; m &= m - 1;
            int hj = __shfl_sync(0xffffffffu, hi, j);
            if (cross && hj < hi) rank++;
        }
        int eid = cross ? (base + rank) : -1;
        int mv = __shfl_sync(0xffffffffu, eid, leaderLane);
        if (lane < n) g_idxmap[slot] = mv;
        if (cross) {
            float t = th[0];
            float s0 = sdf[lo], s1 = sdf[hi];
            if (s0 > 0.f && s1 > 0.f) { s0 -= t; s1 -= t; }
            float inv = 1.f / (s0 - s1);
            float w0 = -s1 * inv, w1 = s0 * inv;
#pragma unroll
            for (int c = 0; c < 3; c++)
                out[eid * 3 + c] = pos[lo * 3 + c] * w0 + pos[hi * 3 + c] * w1;
        }
    } else if (lane == 0) {
        // fallback: row already sorted by k_bcount
        long long prev = -1; int c = 0, mv = -1;
        for (int i = 0; i < n; i++) {
            unsigned long long d = g_bdata[s + i];
            int hv = (int)(d >> 32);
            int slot = (int)(d & 0xffffffffu);
            if (hv != prev) {
                if (occa ^ occ_of(hv)) {
                    int eid = base + c;
                    float t = th[0];
                    float s0 = sdf[lo], s1 = sdf[hv];
                    if (s0 > 0.f && s1 > 0.f) { s0 -= t; s1 -= t; }
                    float inv = 1.f / (s0 - s1);
                    float w0 = -s1 * inv, w1 = s0 * inv;
                    for (int cc = 0; cc < 3; cc++)
                        out[eid * 3 + cc] = pos[lo * 3 + cc] * w0 + pos[hv * 3 + cc] * w1;
                    mv = eid; c++;
                } else mv = -1;
                prev = hv;
            }
            g_idxmap[slot] = mv;
        }
    }
}

__global__ void k_fill_present(int N) {
    int n2 = N + g_meta[4];
    int nw = (n2 + 3) >> 2;
    int i = blockIdx.x * blockDim.x + threadIdx.x;
    if (i < nw) ((int*)g_present)[i] = 0;
}

// fused: faces emission + tetmesh connectivity build + presence marking
__global__ void k_emit(const int4* tet, float* out, int F, int N) {
    int f = blockIdx.x * 256 + threadIdx.x;
    int t = (f < F) ? (int)g_ti[f] : 0;
    int4 cls = cls_block_prefix(t);
    if (f >= F || t == 0) return;
    int4 q = tet[f];
    int qq[4] = {q.x, q.y, q.z, q.w};
    int4* tets4 = (int4*)g_allTets;
    if (t == 15) {
        int NTT3 = g_meta[0] + g_meta[1] - g_meta[2];
        int row = g_meta[2] + 3 * NTT3 + cls.w;
        tets4[row] = q;
#pragma unroll
        for (int j = 0; j < 4; j++) g_present[qq[j]] = 1;
        return;
    }
    int base6 = f * 6;
    int foff = g_meta[6];
    if ((M_NTRI1 >> t) & 1) {
        int row = cls.x;
#pragma unroll
        for (int j = 0; j < 3; j++)
            out[foff + row * 3 + j] = (float)g_idxmap[base6 + c_TRI[t][j]];
    } else {
        int row = g_meta[0] + 2 * cls.y;
#pragma unroll
        for (int j = 0; j < 6; j++)
            out[foff + row * 3 + j] = (float)g_idxmap[base6 + c_TRI[t][j]];
    }
    if ((M_NTET1 >> t) & 1) {
        int row = cls.z;
        int v[4];
#pragma unroll
        for (int j = 0; j < 4; j++) {
            int e = c_TET[t][j];
            v[j] = (e < 4) ? qq[e] : (g_idxmap[base6 + e - 4] + N);
            g_present[v[j]] = 1;
        }
        tets4[row] = make_int4(v[0], v[1], v[2], v[3]);
    } else {
        int row = g_meta[2] + 3 * ((cls.x + cls.y) - cls.z);
#pragma unroll
        for (int rr = 0; rr < 3; rr++) {
            int v[4];
#pragma unroll
            for (int j = 0; j < 4; j++) {
                int e = c_TET[t][rr * 4 + j];
                v[j] = (e < 4) ? qq[e] : (g_idxmap[base6 + e - 4] + N);
                g_present[v[j]] = 1;
            }
            tets4[row + rr] = make_int4(v[0], v[1], v[2], v[3]);
        }
    }
}

__global__ void k_vt(const float* pos, float* out, int N) {
    int n2 = N + g_meta[4];
    int idx = blockIdx.x * blockDim.x + threadIdx.x;
    if (idx >= n2) return;
    if (!g_present[idx]) return;
    int uid = g_presX[idx];
    float x, y, z;
    if (idx < N) {
        x = pos[idx * 3 + 0]; y = pos[idx * 3 + 1]; z = pos[idx * 3 + 2];
    } else {
        int e = idx - N;
        x = out[e * 3 + 0]; y = out[e * 3 + 1]; z = out[e * 3 + 2];
    }
    int o = g_meta[8];
    out[o + uid * 3 + 0] = x;
    out[o + uid * 3 + 1] = y;
    out[o + uid * 3 + 2] = z;
}

__global__ void k_tout(float* out) {
    int row = blockIdx.x * blockDim.x + threadIdx.x;
    if (row >= g_meta[7]) return;
    int4 v = ((const int4*)g_allTets)[row];
    int o = g_meta[9] + row * 4;
    out[o + 0] = (float)g_presX[v.x];
    out[o + 1] = (float)g_presX[v.y];
    out[o + 2] = (float)g_presX[v.z];
    out[o + 3] = (float)g_presX[v.w];
}

// ---------------------------------------------------------------------------
// host launcher
// ---------------------------------------------------------------------------
static inline int gb(long long n) { return (int)((n + 255) / 256); }

extern "C" void kernel_launch(void* const* d_in, const int* in_sizes, int n_in,
                              void* d_out, int out_size) {
    const float* pos = (const float*)d_in[0];
    const float* sdf = (const float*)d_in[1];
    const int4* tet = (const int4*)d_in[2];
    const float* thick = (const float*)d_in[3];
    float* out = (float*)d_out;

    int N = in_sizes[1];
    int F = in_sizes[2] / 4;
    if (N > MAXN) N = MAXN;
    if (F > MAXF) F = MAXF;
    int NW = (N + 31) / 32;
    int PL = N + MAXS;
    int NB = 2 * N;                    // buckets (lo, hi-half)
    int NHALF = N / 2;

    int *p_crossCnt, *p_crossX, *p_bsums;
    cudaGetSymbolAddress((void**)&p_crossCnt, g_crossCnt);
    cudaGetSymbolAddress((void**)&p_crossX, g_crossX);
    cudaGetSymbolAddress((void**)&p_bsums, g_bsums);

    int nbF = (F + 255) / 256;          // tet-domain blocks
    int nbB = (NB + 2047) / 2048;       // bucket-domain scan blocks
    int nbP = (PL + 2047) / 2048;       // presence scan blocks (worst case)

    // 1. occupancy bitmask (+bcnt reset), then fused ti + cls sums + scatter
    k_occbits<<<gb((long long)NW * 32), 256>>>(sdf, thick, N, NW);
    k_ti_scatter<<<nbF, 256>>>(tet, F, NHALF);
    k_scan_singleP<<<1, 1024>>>(nbF);   // -> per-block cls bases + meta[0..3]

    // 2. crossing counts (match_any, no sort) -> prefix -> assignment + verts
    k_bcount<<<gb((long long)NB * 32), 256>>>(NB);
    k_scan_partial_int<<<nbB, 256>>>(p_crossCnt, NB, p_bsums);
    k_scan_single<<<1, 1024>>>(p_bsums, nbB, 1);   // sets E + offsets
    k_scan_final_int<<<nbB, 256>>>(p_crossCnt, NB, p_bsums, p_crossX);
    k_fill_present<<<gb(PL / 4), 256>>>(N);
    k_bemit<<<gb((long long)NB * 32), 256>>>(pos, sdf, thick, out, NB);

    // 3. faces + tets + presence marks (fused)
    k_emit<<<nbF, 256>>>(tet, out, F, N);

    // 4. presence scan over [0, N+E) -> sorted-unique ids (+U, tetsOff)
    k_scan_partial_u8d<<<nbP, 256>>>(N, p_bsums);
    k_scan_single<<<1, 1024>>>(p_bsums, nbP, 2);
    k_scan_final_u8d<<<nbP, 256>>>(N, p_bsums);

    // 5. verts_tetmesh (region 2) + tets_tetmesh (region 3)
    k_vt<<<gb(PL), 256>>>(pos, out, N);
    k_tout<<<gb(MAXTE / 4), 256>>>(out);
}